// round 4
// baseline (speedup 1.0000x reference)
#include <cuda_runtime.h>
#include <cstdint>

// Shapes (fixed):
//   z:     [16, 128, 32, 32] f32   (B=16, C=128=L*D, H=W=32)
//   codes: [8, 512, 16]      f32   (L=8, K=512, D=16)
// d_out (f32): soft[16384*128] | hard[16384*128] | idx[16384*8]

#define KN   512
#define DN   16
#define LN   8
#define NPOS 16384
#define HN   (NPOS * 128)

typedef unsigned long long f2;  // packed f32x2

__device__ __forceinline__ f2 pack2(float lo, float hi) {
    f2 r; asm("mov.b64 %0, {%1,%2};" : "=l"(r) : "f"(lo), "f"(hi)); return r;
}
__device__ __forceinline__ void unpack2(f2 v, float& lo, float& hi) {
    asm("mov.b64 {%0,%1}, %2;" : "=f"(lo), "=f"(hi) : "l"(v));
}
__device__ __forceinline__ f2 mul2(f2 a, f2 b) {
    f2 d; asm("mul.rn.f32x2 %0, %1, %2;" : "=l"(d) : "l"(a), "l"(b)); return d;
}
__device__ __forceinline__ f2 add2(f2 a, f2 b) {
    f2 d; asm("add.rn.f32x2 %0, %1, %2;" : "=l"(d) : "l"(a), "l"(b)); return d;
}
__device__ __forceinline__ f2 fma2(f2 a, f2 b, f2 c) {
    f2 d; asm("fma.rn.f32x2 %0, %1, %2, %3;" : "=l"(d) : "l"(a), "l"(b), "l"(c)); return d;
}
__device__ __forceinline__ float sqrt_approx(float x) {
    float r; asm("sqrt.approx.f32 %0, %1;" : "=f"(r) : "f"(x)); return r;
}
__device__ __forceinline__ float expneg_approx(float x) {   // e^{-x} via ex2
    float r;
    asm("mul.f32 %0, %1, 0fBFB8AA3B;\n\tex2.approx.f32 %0, %0;" : "=f"(r) : "f"(x));
    return r;
}

// exact d2 in reference order (used only in the rare rescan path)
__device__ __forceinline__ float d2_exact(const float* __restrict__ h, float h2,
                                          const float* __restrict__ c, float w2) {
    float dot = 0.f;
    #pragma unroll
    for (int d = 0; d < DN; d++) dot = fmaf(h[d], c[d], dot);
    float t = fmaf(-2.0f, dot, h2);   // == fl(h2 - fl(2*dot)), 2*dot exact
    return __fadd_rn(t, w2);
}

__global__ __launch_bounds__(256, 3)
void vq_kernel(const float* __restrict__ z,
               const float* __restrict__ codes,
               float* __restrict__ out,
               int out_size)
{
    __shared__ __align__(16) float cs[KN * DN];   // codes[l], [k][d], 32 KB
    __shared__ float w2s[KN];                     // ||codes[l][k]||^2 (ref order)

    const int l = blockIdx.y;
    const int n = blockIdx.x * blockDim.x + threadIdx.x;
    const int b = n >> 10;
    const int s = n & 1023;

    // ---- cooperative load of codes[l] ----
    {
        const float4* cg = reinterpret_cast<const float4*>(codes + (size_t)l * KN * DN);
        float4* cs4 = reinterpret_cast<float4*>(cs);
        #pragma unroll 4
        for (int i = threadIdx.x; i < KN * DN / 4; i += 256) cs4[i] = cg[i];
    }
    __syncthreads();
    for (int k = threadIdx.x; k < KN; k += 256) {
        const float* c = cs + k * DN;
        float a = 0.f;
        #pragma unroll
        for (int d = 0; d < DN; d++) a = __fadd_rn(a, __fmul_rn(c[d], c[d]));
        w2s[k] = a;
    }
    __syncthreads();

    // ---- h for this (position, l) ----
    const float* zb = z + (size_t)b * (128 * 1024) + (size_t)(l * DN) * 1024 + s;
    float h[DN];
    #pragma unroll
    for (int d = 0; d < DN; d++) h[d] = zb[(size_t)d * 1024];
    float h2 = 0.f;                                  // exact ref order
    #pragma unroll
    for (int d = 0; d < DN; d++) h2 = __fadd_rn(h2, __fmul_rn(h[d], h[d]));

    f2 hp[8];
    #pragma unroll
    for (int i = 0; i < 8; i++) hp[i] = pack2(h[2 * i], h[2 * i + 1]);

    // ---- main loop: packed dot, approx argmin with guard band ----
    float best0 = 3.4e38f, best1 = 3.4e38f;
    int   k0 = 0;
    float S = 0.f;
    f2 acc[8];
    #pragma unroll
    for (int i = 0; i < 8; i++) acc[i] = 0ull;

    const ulonglong2* qp = reinterpret_cast<const ulonglong2*>(cs);

    #pragma unroll 4
    for (int k = 0; k < KN; k++) {
        ulonglong2 A = qp[k * 4 + 0];   // {q0,q1}
        ulonglong2 B = qp[k * 4 + 1];   // {q2,q3}
        ulonglong2 C = qp[k * 4 + 2];   // {q4,q5}
        ulonglong2 D = qp[k * 4 + 3];   // {q6,q7}

        // dot via 4 independent packed chains
        f2 c0 = mul2(hp[0], A.x);
        f2 c1 = mul2(hp[1], A.y);
        f2 c2 = mul2(hp[2], B.x);
        f2 c3 = mul2(hp[3], B.y);
        c0 = fma2(hp[4], C.x, c0);
        c1 = fma2(hp[5], C.y, c1);
        c2 = fma2(hp[6], D.x, c2);
        c3 = fma2(hp[7], D.y, c3);
        c0 = add2(c0, c1);
        c2 = add2(c2, c3);
        c0 = add2(c0, c2);
        float lo, hi; unpack2(c0, lo, hi);
        float dot = lo + hi;

        float d2 = __fadd_rn(fmaf(-2.0f, dot, h2), w2s[k]);

        // approx argmin (first index) + value-only runner-up
        float b0_old = best0;
        bool lt0 = d2 < best0;
        best0 = lt0 ? d2 : best0;
        k0    = lt0 ? k  : k0;
        best1 = fminf(best1, fmaxf(b0_old, d2));

        // softmax path (loose tolerance)
        float dist = sqrt_approx(fmaxf(d2, 1e-12f));
        float w = expneg_approx(dist);       // in (3e-7, 1]
        S += w;
        f2 wp = pack2(w, w);
        acc[0] = fma2(wp, A.x, acc[0]);
        acc[1] = fma2(wp, A.y, acc[1]);
        acc[2] = fma2(wp, B.x, acc[2]);
        acc[3] = fma2(wp, B.y, acc[3]);
        acc[4] = fma2(wp, C.x, acc[4]);
        acc[5] = fma2(wp, C.y, acc[5]);
        acc[6] = fma2(wp, D.x, acc[6]);
        acc[7] = fma2(wp, D.y, acc[7]);
    }

    // ---- argmin guard: if top-2 gap is inside the ordering-error band,
    //      redo the decision with the exact reference rule ----
    int bk = k0;
    if (best1 - best0 < 5e-4f) {
        float hs[DN];
        #pragma unroll
        for (int i = 0; i < 8; i++) unpack2(hp[i], hs[2 * i], hs[2 * i + 1]);
        float minv = 3.4e38f;
        for (int k = 0; k < KN; k++) {
            float d2 = d2_exact(hs, h2, cs + k * DN, w2s[k]);
            float sd = __fsqrt_rn(fmaxf(d2, 1e-12f));
            if (sd < minv) { minv = sd; bk = k; }   // first index of fp32 min
        }
    }

    // ---- epilogue ----
    float inv = 1.0f / S;
    float so[DN];
    #pragma unroll
    for (int i = 0; i < 8; i++) unpack2(acc[i], so[2 * i], so[2 * i + 1]);

    {
        float4* o4 = reinterpret_cast<float4*>(out + (size_t)n * 128 + l * DN);
        #pragma unroll
        for (int j = 0; j < 4; j++) {
            float4 v;
            v.x = so[4 * j + 0] * inv;
            v.y = so[4 * j + 1] * inv;
            v.z = so[4 * j + 2] * inv;
            v.w = so[4 * j + 3] * inv;
            o4[j] = v;
        }
    }
    if (out_size >= 2 * HN) {
        const float4* cr = reinterpret_cast<const float4*>(cs + bk * DN);
        float4* ho = reinterpret_cast<float4*>(out + HN + (size_t)n * 128 + l * DN);
        #pragma unroll
        for (int j = 0; j < 4; j++) ho[j] = cr[j];
    }
    if (out_size >= 2 * HN + NPOS * LN) {
        out[2 * HN + (size_t)n * LN + l] = (float)bk;
    }
}

extern "C" void kernel_launch(void* const* d_in, const int* in_sizes, int n_in,
                              void* d_out, int out_size) {
    const float* z     = (const float*)d_in[0];
    const float* codes = (const float*)d_in[1];
    float* out = (float*)d_out;

    dim3 grid(NPOS / 256, LN);   // (64, 8)
    vq_kernel<<<grid, 256>>>(z, codes, out, out_size);
}

// round 5
// speedup vs baseline: 1.3446x; 1.3446x over previous
#include <cuda_runtime.h>
#include <cstdint>

// Shapes (fixed):
//   z:     [16, 128, 32, 32] f32   (B=16, C=128=L*D, H=W=32)
//   codes: [8, 512, 16]      f32   (L=8, K=512, D=16)
// d_out (f32): soft[16384*128] | hard[16384*128] | idx[16384*8]

#define KN   512
#define DN   16
#define LN   8
#define NPOS 16384
#define HN   (NPOS * 128)

typedef unsigned long long f2;  // packed f32x2

__device__ __forceinline__ f2 pack2(float lo, float hi) {
    f2 r; asm("mov.b64 %0, {%1,%2};" : "=l"(r) : "f"(lo), "f"(hi)); return r;
}
__device__ __forceinline__ void unpack2(f2 v, float& lo, float& hi) {
    asm("mov.b64 {%0,%1}, %2;" : "=f"(lo), "=f"(hi) : "l"(v));
}
__device__ __forceinline__ f2 fma2(f2 a, f2 b, f2 c) {
    f2 d; asm("fma.rn.f32x2 %0, %1, %2, %3;" : "=l"(d) : "l"(a), "l"(b), "l"(c)); return d;
}
__device__ __forceinline__ float sqrt_approx(float x) {
    float r; asm("sqrt.approx.f32 %0, %1;" : "=f"(r) : "f"(x)); return r;
}
__device__ __forceinline__ float expneg_approx(float x) {   // e^{-x}
    float r;
    asm("mul.f32 %0, %1, 0fBFB8AA3B;\n\tex2.approx.f32 %0, %0;" : "=f"(r) : "f"(x));
    return r;
}

// exact d2 in reference order (rescan path only)
__device__ __forceinline__ float d2_exact(const float* __restrict__ h, float h2,
                                          const float* __restrict__ c, float w2) {
    float dot = 0.f;
    #pragma unroll
    for (int d = 0; d < DN; d++) dot = fmaf(h[d], c[d], dot);
    float t = fmaf(-2.0f, dot, h2);   // == fl(h2 - fl(2*dot)), 2*dot exact
    return __fadd_rn(t, w2);
}

struct PosState {
    float h[DN];
    float h2;
    float best0, best1;
    int   k0;
    float S;
    f2    acc[8];
};

__device__ __forceinline__ void pos_init(PosState& P, const float* __restrict__ zb) {
    #pragma unroll
    for (int d = 0; d < DN; d++) P.h[d] = zb[(size_t)d * 1024];
    P.h2 = 0.f;
    #pragma unroll
    for (int d = 0; d < DN; d++) P.h2 = __fadd_rn(P.h2, __fmul_rn(P.h[d], P.h[d]));
    P.best0 = 3.4e38f; P.best1 = 3.4e38f; P.k0 = 0; P.S = 0.f;
    #pragma unroll
    for (int i = 0; i < 8; i++) P.acc[i] = 0ull;
}

__device__ __forceinline__ void pos_step(PosState& P, int k,
                                         const float4& qa, const float4& qb,
                                         const float4& qc, const float4& qd,
                                         float w2) {
    // exact sequential dot (reference contraction order)
    float dot = 0.f;
    dot = fmaf(P.h[0],  qa.x, dot); dot = fmaf(P.h[1],  qa.y, dot);
    dot = fmaf(P.h[2],  qa.z, dot); dot = fmaf(P.h[3],  qa.w, dot);
    dot = fmaf(P.h[4],  qb.x, dot); dot = fmaf(P.h[5],  qb.y, dot);
    dot = fmaf(P.h[6],  qb.z, dot); dot = fmaf(P.h[7],  qb.w, dot);
    dot = fmaf(P.h[8],  qc.x, dot); dot = fmaf(P.h[9],  qc.y, dot);
    dot = fmaf(P.h[10], qc.z, dot); dot = fmaf(P.h[11], qc.w, dot);
    dot = fmaf(P.h[12], qd.x, dot); dot = fmaf(P.h[13], qd.y, dot);
    dot = fmaf(P.h[14], qd.z, dot); dot = fmaf(P.h[15], qd.w, dot);

    float d2 = __fadd_rn(fmaf(-2.0f, dot, P.h2), w2);

    // first-index argmin + value-only runner-up
    float b0_old = P.best0;
    bool lt0 = d2 < P.best0;
    P.best0 = lt0 ? d2 : P.best0;
    P.k0    = lt0 ? k  : P.k0;
    P.best1 = fminf(P.best1, fmaxf(b0_old, d2));

    // softmax (loose tolerance)
    float dist = sqrt_approx(fmaxf(d2, 1e-12f));
    float w = expneg_approx(dist);
    P.S += w;
    f2 wp = pack2(w, w);
    P.acc[0] = fma2(wp, pack2(qa.x, qa.y), P.acc[0]);
    P.acc[1] = fma2(wp, pack2(qa.z, qa.w), P.acc[1]);
    P.acc[2] = fma2(wp, pack2(qb.x, qb.y), P.acc[2]);
    P.acc[3] = fma2(wp, pack2(qb.z, qb.w), P.acc[3]);
    P.acc[4] = fma2(wp, pack2(qc.x, qc.y), P.acc[4]);
    P.acc[5] = fma2(wp, pack2(qc.z, qc.w), P.acc[5]);
    P.acc[6] = fma2(wp, pack2(qd.x, qd.y), P.acc[6]);
    P.acc[7] = fma2(wp, pack2(qd.z, qd.w), P.acc[7]);
}

__device__ __forceinline__ void pos_finish(PosState& P, int n, int l,
                                           const float* __restrict__ cs,
                                           const float* __restrict__ w2s,
                                           float* __restrict__ out, int out_size) {
    // resolve argmin with reference sqrt-plateau tie rule
    float s0 = __fsqrt_rn(fmaxf(P.best0, 1e-12f));
    float s1 = __fsqrt_rn(fmaxf(P.best1, 1e-12f));
    int bk = P.k0;
    if (s1 == s0) {
        for (int k = 0; k < KN; k++) {
            float d2 = d2_exact(P.h, P.h2, cs + k * DN, w2s[k]);
            if (__fsqrt_rn(fmaxf(d2, 1e-12f)) == s0) { bk = k; break; }
        }
    }

    float inv = 1.0f / P.S;
    float so[DN];
    #pragma unroll
    for (int i = 0; i < 8; i++) unpack2(P.acc[i], so[2 * i], so[2 * i + 1]);

    {
        float4* o4 = reinterpret_cast<float4*>(out + (size_t)n * 128 + l * DN);
        #pragma unroll
        for (int j = 0; j < 4; j++) {
            float4 v;
            v.x = so[4 * j + 0] * inv;
            v.y = so[4 * j + 1] * inv;
            v.z = so[4 * j + 2] * inv;
            v.w = so[4 * j + 3] * inv;
            o4[j] = v;
        }
    }
    if (out_size >= 2 * HN) {
        const float4* cr = reinterpret_cast<const float4*>(cs + bk * DN);
        float4* ho = reinterpret_cast<float4*>(out + HN + (size_t)n * 128 + l * DN);
        #pragma unroll
        for (int j = 0; j < 4; j++) ho[j] = cr[j];
    }
    if (out_size >= 2 * HN + NPOS * LN) {
        out[2 * HN + (size_t)n * LN + l] = (float)bk;
    }
}

__global__ __launch_bounds__(128, 4)
void vq_kernel(const float* __restrict__ z,
               const float* __restrict__ codes,
               float* __restrict__ out,
               int out_size)
{
    __shared__ __align__(16) float cs[KN * DN];   // codes[l], [k][d], 32 KB
    __shared__ float w2s[KN];                     // ||codes[l][k]||^2 (ref order)

    const int l  = blockIdx.y;
    const int n0 = blockIdx.x * 256 + threadIdx.x;       // first position
    const int n1 = n0 + 128;                             // second position
    const int b0 = n0 >> 10, s0 = n0 & 1023;
    const int b1 = n1 >> 10, s1 = n1 & 1023;

    // cooperative load of codes[l]
    {
        const float4* cg = reinterpret_cast<const float4*>(codes + (size_t)l * KN * DN);
        float4* cs4 = reinterpret_cast<float4*>(cs);
        #pragma unroll 4
        for (int i = threadIdx.x; i < KN * DN / 4; i += 128) cs4[i] = cg[i];
    }
    __syncthreads();
    for (int k = threadIdx.x; k < KN; k += 128) {
        const float* c = cs + k * DN;
        float a = 0.f;
        #pragma unroll
        for (int d = 0; d < DN; d++) a = __fadd_rn(a, __fmul_rn(c[d], c[d]));
        w2s[k] = a;
    }
    __syncthreads();

    PosState A, B;
    pos_init(A, z + (size_t)b0 * (128 * 1024) + (size_t)(l * DN) * 1024 + s0);
    pos_init(B, z + (size_t)b1 * (128 * 1024) + (size_t)(l * DN) * 1024 + s1);

    const float4* q4 = reinterpret_cast<const float4*>(cs);

    #pragma unroll 2
    for (int k = 0; k < KN; k++) {
        float4 qa = q4[k * 4 + 0];
        float4 qb = q4[k * 4 + 1];
        float4 qc = q4[k * 4 + 2];
        float4 qd = q4[k * 4 + 3];
        float  w2 = w2s[k];
        pos_step(A, k, qa, qb, qc, qd, w2);
        pos_step(B, k, qa, qb, qc, qd, w2);
    }

    pos_finish(A, n0, l, cs, w2s, out, out_size);
    pos_finish(B, n1, l, cs, w2s, out, out_size);
}

extern "C" void kernel_launch(void* const* d_in, const int* in_sizes, int n_in,
                              void* d_out, int out_size) {
    const float* z     = (const float*)d_in[0];
    const float* codes = (const float*)d_in[1];
    float* out = (float*)d_out;

    dim3 grid(NPOS / 256, LN);   // (64, 8) blocks of 128 threads, 2 pos/thread
    vq_kernel<<<grid, 128>>>(z, codes, out, out_size);
}

// round 6
// speedup vs baseline: 1.4705x; 1.0936x over previous
#include <cuda_runtime.h>
#include <cstdint>

// Shapes (fixed):
//   z:     [16, 128, 32, 32] f32   (B=16, C=128=L*D, H=W=32)
//   codes: [8, 512, 16]      f32   (L=8, K=512, D=16)
// d_out (f32): soft[16384*128] | hard[16384*128] | idx[16384*8]

#define KN   512
#define DN   16
#define LN   8
#define NPOS 16384
#define HN   (NPOS * 128)

typedef unsigned long long f2;  // packed f32x2

__device__ __forceinline__ f2 pack2(float lo, float hi) {
    f2 r; asm("mov.b64 %0, {%1,%2};" : "=l"(r) : "f"(lo), "f"(hi)); return r;
}
__device__ __forceinline__ void unpack2(f2 v, float& lo, float& hi) {
    asm("mov.b64 {%0,%1}, %2;" : "=f"(lo), "=f"(hi) : "l"(v));
}
__device__ __forceinline__ f2 fma2(f2 a, f2 b, f2 c) {
    f2 d; asm("fma.rn.f32x2 %0, %1, %2, %3;" : "=l"(d) : "l"(a), "l"(b), "l"(c)); return d;
}
__device__ __forceinline__ float sqrt_approx(float x) {
    float r; asm("sqrt.approx.f32 %0, %1;" : "=f"(r) : "f"(x)); return r;
}
__device__ __forceinline__ float expneg_approx(float x) {   // e^{-x}
    float r;
    asm("mul.f32 %0, %1, 0fBFB8AA3B;\n\tex2.approx.f32 %0, %0;" : "=f"(r) : "f"(x));
    return r;
}

// exact d2 in reference order (rescan path only)
__device__ __forceinline__ float d2_exact(const float* __restrict__ h, float h2,
                                          const float* __restrict__ c, float w2) {
    float dot = 0.f;
    #pragma unroll
    for (int d = 0; d < DN; d++) dot = fmaf(h[d], c[d], dot);
    float t = fmaf(-2.0f, dot, h2);   // == fl(h2 - fl(2*dot)), 2*dot exact
    return __fadd_rn(t, w2);
}

__global__ __launch_bounds__(128, 4)
void vq_kernel(const float* __restrict__ z,
               const float* __restrict__ codes,
               float* __restrict__ out,
               int out_size)
{
    __shared__ __align__(16) float cs[KN * DN];   // codes[l], [k][d], 32 KB
    __shared__ float w2s[KN];                     // ||codes[l][k]||^2 (ref order)

    const int l  = blockIdx.y;
    const int n0 = blockIdx.x * 256 + threadIdx.x;   // position A
    const int n1 = n0 + 128;                         // position B
    const int b0 = n0 >> 10, s0i = n0 & 1023;
    const int b1 = n1 >> 10, s1i = n1 & 1023;

    // ---- cooperative load of codes[l] ----
    {
        const float4* cg = reinterpret_cast<const float4*>(codes + (size_t)l * KN * DN);
        float4* cs4 = reinterpret_cast<float4*>(cs);
        #pragma unroll 4
        for (int i = threadIdx.x; i < KN * DN / 4; i += 128) cs4[i] = cg[i];
    }
    __syncthreads();
    for (int k = threadIdx.x; k < KN; k += 128) {
        const float* c = cs + k * DN;
        float a = 0.f;
        #pragma unroll
        for (int d = 0; d < DN; d++) a = __fadd_rn(a, __fmul_rn(c[d], c[d]));
        w2s[k] = a;
    }
    __syncthreads();

    // ---- per-position state ----
    float hA[DN], hB[DN];
    {
        const float* za = z + (size_t)b0 * (128 * 1024) + (size_t)(l * DN) * 1024 + s0i;
        const float* zb = z + (size_t)b1 * (128 * 1024) + (size_t)(l * DN) * 1024 + s1i;
        #pragma unroll
        for (int d = 0; d < DN; d++) hA[d] = za[(size_t)d * 1024];
        #pragma unroll
        for (int d = 0; d < DN; d++) hB[d] = zb[(size_t)d * 1024];
    }
    float h2A = 0.f, h2B = 0.f;
    #pragma unroll
    for (int d = 0; d < DN; d++) h2A = __fadd_rn(h2A, __fmul_rn(hA[d], hA[d]));
    #pragma unroll
    for (int d = 0; d < DN; d++) h2B = __fadd_rn(h2B, __fmul_rn(hB[d], hB[d]));

    float bA0 = 3.4e38f, bA1 = 3.4e38f, bB0 = 3.4e38f, bB1 = 3.4e38f;
    int   kA0 = 0, kB0 = 0;
    float SA = 0.f, SB = 0.f;
    f2 accA[8], accB[8];
    #pragma unroll
    for (int i = 0; i < 8; i++) { accA[i] = 0ull; accB[i] = 0ull; }

    const ulonglong2* qp = reinterpret_cast<const ulonglong2*>(cs);

    #pragma unroll 4
    for (int k = 0; k < KN; k++) {
        ulonglong2 A = qp[k * 4 + 0];   // q pairs {0,1}
        ulonglong2 B = qp[k * 4 + 1];   // {2,3}
        ulonglong2 C = qp[k * 4 + 2];   // {4,5}
        ulonglong2 D = qp[k * 4 + 3];   // {6,7}
        float w2 = w2s[k];

        // scalars (shared by both positions; unpack is alias-eliminable)
        float q0,q1,q2,q3,q4,q5,q6,q7,q8,q9,q10,q11,q12,q13,q14,q15;
        unpack2(A.x, q0,  q1);  unpack2(A.y, q2,  q3);
        unpack2(B.x, q4,  q5);  unpack2(B.y, q6,  q7);
        unpack2(C.x, q8,  q9);  unpack2(C.y, q10, q11);
        unpack2(D.x, q12, q13); unpack2(D.y, q14, q15);

        // exact sequential dots (reference contraction order)
        float dA = 0.f, dB = 0.f;
        dA = fmaf(hA[0],q0,dA);   dB = fmaf(hB[0],q0,dB);
        dA = fmaf(hA[1],q1,dA);   dB = fmaf(hB[1],q1,dB);
        dA = fmaf(hA[2],q2,dA);   dB = fmaf(hB[2],q2,dB);
        dA = fmaf(hA[3],q3,dA);   dB = fmaf(hB[3],q3,dB);
        dA = fmaf(hA[4],q4,dA);   dB = fmaf(hB[4],q4,dB);
        dA = fmaf(hA[5],q5,dA);   dB = fmaf(hB[5],q5,dB);
        dA = fmaf(hA[6],q6,dA);   dB = fmaf(hB[6],q6,dB);
        dA = fmaf(hA[7],q7,dA);   dB = fmaf(hB[7],q7,dB);
        dA = fmaf(hA[8],q8,dA);   dB = fmaf(hB[8],q8,dB);
        dA = fmaf(hA[9],q9,dA);   dB = fmaf(hB[9],q9,dB);
        dA = fmaf(hA[10],q10,dA); dB = fmaf(hB[10],q10,dB);
        dA = fmaf(hA[11],q11,dA); dB = fmaf(hB[11],q11,dB);
        dA = fmaf(hA[12],q12,dA); dB = fmaf(hB[12],q12,dB);
        dA = fmaf(hA[13],q13,dA); dB = fmaf(hB[13],q13,dB);
        dA = fmaf(hA[14],q14,dA); dB = fmaf(hB[14],q14,dB);
        dA = fmaf(hA[15],q15,dA); dB = fmaf(hB[15],q15,dB);

        float d2A = __fadd_rn(fmaf(-2.0f, dA, h2A), w2);
        float d2B = __fadd_rn(fmaf(-2.0f, dB, h2B), w2);

        // first-index argmin + value-only runner-up
        float oA = bA0; bool lA = d2A < bA0;
        bA0 = lA ? d2A : bA0;  kA0 = lA ? k : kA0;
        bA1 = fminf(bA1, fmaxf(oA, d2A));
        float oB = bB0; bool lB = d2B < bB0;
        bB0 = lB ? d2B : bB0;  kB0 = lB ? k : kB0;
        bB1 = fminf(bB1, fmaxf(oB, d2B));

        // softmax weights
        float wA = expneg_approx(sqrt_approx(fmaxf(d2A, 1e-12f)));
        float wB = expneg_approx(sqrt_approx(fmaxf(d2B, 1e-12f)));
        SA += wA;  SB += wB;
        f2 wpA = pack2(wA, wA);
        f2 wpB = pack2(wB, wB);
        accA[0] = fma2(wpA, A.x, accA[0]);  accB[0] = fma2(wpB, A.x, accB[0]);
        accA[1] = fma2(wpA, A.y, accA[1]);  accB[1] = fma2(wpB, A.y, accB[1]);
        accA[2] = fma2(wpA, B.x, accA[2]);  accB[2] = fma2(wpB, B.x, accB[2]);
        accA[3] = fma2(wpA, B.y, accA[3]);  accB[3] = fma2(wpB, B.y, accB[3]);
        accA[4] = fma2(wpA, C.x, accA[4]);  accB[4] = fma2(wpB, C.x, accB[4]);
        accA[5] = fma2(wpA, C.y, accA[5]);  accB[5] = fma2(wpB, C.y, accB[5]);
        accA[6] = fma2(wpA, D.x, accA[6]);  accB[6] = fma2(wpB, D.x, accB[6]);
        accA[7] = fma2(wpA, D.y, accA[7]);  accB[7] = fma2(wpB, D.y, accB[7]);
    }

    // ---- finish both positions ----
    #pragma unroll
    for (int p = 0; p < 2; p++) {
        const float* h  = p ? hB : hA;
        float h2    = p ? h2B : h2A;
        float best0 = p ? bB0 : bA0;
        float best1 = p ? bB1 : bA1;
        int   k0    = p ? kB0 : kA0;
        float S     = p ? SB  : SA;
        const f2* acc = p ? accB : accA;
        int n       = p ? n1 : n0;

        float sq0 = __fsqrt_rn(fmaxf(best0, 1e-12f));
        float sq1 = __fsqrt_rn(fmaxf(best1, 1e-12f));
        int bk = k0;
        if (sq1 == sq0) {   // plateau tie (rare): exact first-index rule
            for (int k = 0; k < KN; k++) {
                float d2 = d2_exact(h, h2, cs + k * DN, w2s[k]);
                if (__fsqrt_rn(fmaxf(d2, 1e-12f)) == sq0) { bk = k; break; }
            }
        }

        float inv = 1.0f / S;
        float so[DN];
        #pragma unroll
        for (int i = 0; i < 8; i++) unpack2(acc[i], so[2 * i], so[2 * i + 1]);

        float4* o4 = reinterpret_cast<float4*>(out + (size_t)n * 128 + l * DN);
        #pragma unroll
        for (int j = 0; j < 4; j++) {
            float4 v;
            v.x = so[4 * j + 0] * inv;
            v.y = so[4 * j + 1] * inv;
            v.z = so[4 * j + 2] * inv;
            v.w = so[4 * j + 3] * inv;
            o4[j] = v;
        }
        if (out_size >= 2 * HN) {
            const float4* cr = reinterpret_cast<const float4*>(cs + bk * DN);
            float4* ho = reinterpret_cast<float4*>(out + HN + (size_t)n * 128 + l * DN);
            #pragma unroll
            for (int j = 0; j < 4; j++) ho[j] = cr[j];
        }
        if (out_size >= 2 * HN + NPOS * LN) {
            out[2 * HN + (size_t)n * LN + l] = (float)bk;
        }
    }
}

extern "C" void kernel_launch(void* const* d_in, const int* in_sizes, int n_in,
                              void* d_out, int out_size) {
    const float* z     = (const float*)d_in[0];
    const float* codes = (const float*)d_in[1];
    float* out = (float*)d_out;

    dim3 grid(NPOS / 256, LN);   // (64, 8) blocks of 128 threads, 2 pos/thread
    vq_kernel<<<grid, 128>>>(z, codes, out, out_size);
}

// round 7
// speedup vs baseline: 1.6185x; 1.1006x over previous
#include <cuda_runtime.h>
#include <cstdint>

// Shapes (fixed):
//   z:     [16, 128, 32, 32] f32   (B=16, C=128=L*D, H=W=32)
//   codes: [8, 512, 16]      f32   (L=8, K=512, D=16)
// d_out (f32): soft[16384*128] | hard[16384*128] | idx[16384*8]

#define KN   512
#define DN   16
#define LN   8
#define NPOS 16384
#define HN   (NPOS * 128)
#define BLKPOS 222               // positions per block (74 blocks/l)

typedef unsigned long long f2;  // packed f32x2

__device__ __forceinline__ f2 pack2(float lo, float hi) {
    f2 r; asm("mov.b64 %0, {%1,%2};" : "=l"(r) : "f"(lo), "f"(hi)); return r;
}
__device__ __forceinline__ void unpack2(f2 v, float& lo, float& hi) {
    asm("mov.b64 {%0,%1}, %2;" : "=f"(lo), "=f"(hi) : "l"(v));
}
__device__ __forceinline__ f2 fma2(f2 a, f2 b, f2 c) {
    f2 d; asm("fma.rn.f32x2 %0, %1, %2, %3;" : "=l"(d) : "l"(a), "l"(b), "l"(c)); return d;
}
__device__ __forceinline__ float sqrt_approx(float x) {
    float r; asm("sqrt.approx.f32 %0, %1;" : "=f"(r) : "f"(x)); return r;
}
__device__ __forceinline__ float expneg_approx(float x) {   // e^{-x}
    float r;
    asm("mul.f32 %0, %1, 0fBFB8AA3B;\n\tex2.approx.f32 %0, %0;" : "=f"(r) : "f"(x));
    return r;
}

// exact d2 in reference order (rescan path only)
__device__ __forceinline__ float d2_exact(const float* __restrict__ h, float h2,
                                          const float* __restrict__ c, float w2) {
    float dot = 0.f;
    #pragma unroll
    for (int d = 0; d < DN; d++) dot = fmaf(h[d], c[d], dot);
    float t = fmaf(-2.0f, dot, h2);   // == fl(h2 - fl(2*dot)), 2*dot exact
    return __fadd_rn(t, w2);
}

__device__ __forceinline__ void finish_pos(
    const float* __restrict__ h, float h2, float best0, float best1, int k0,
    float S, const f2* __restrict__ acc, int n, int l,
    const float* __restrict__ cs, const float* __restrict__ w2s,
    float* __restrict__ out, int out_size)
{
    float sq0 = __fsqrt_rn(fmaxf(best0, 1e-12f));
    float sq1 = __fsqrt_rn(fmaxf(best1, 1e-12f));
    int bk = k0;
    if (sq1 == sq0) {   // plateau tie (rare): exact first-index rule
        for (int k = 0; k < KN; k++) {
            float d2 = d2_exact(h, h2, cs + k * DN, w2s[k]);
            if (__fsqrt_rn(fmaxf(d2, 1e-12f)) == sq0) { bk = k; break; }
        }
    }

    float inv = 1.0f / S;
    float so[DN];
    #pragma unroll
    for (int i = 0; i < 8; i++) unpack2(acc[i], so[2 * i], so[2 * i + 1]);

    float4* o4 = reinterpret_cast<float4*>(out + (size_t)n * 128 + l * DN);
    #pragma unroll
    for (int j = 0; j < 4; j++) {
        float4 v;
        v.x = so[4 * j + 0] * inv;
        v.y = so[4 * j + 1] * inv;
        v.z = so[4 * j + 2] * inv;
        v.w = so[4 * j + 3] * inv;
        o4[j] = v;
    }
    if (out_size >= 2 * HN) {
        const float4* cr = reinterpret_cast<const float4*>(cs + bk * DN);
        float4* ho = reinterpret_cast<float4*>(out + HN + (size_t)n * 128 + l * DN);
        #pragma unroll
        for (int j = 0; j < 4; j++) ho[j] = cr[j];
    }
    if (out_size >= 2 * HN + NPOS * LN) {
        out[2 * HN + (size_t)n * LN + l] = (float)bk;
    }
}

template<bool DO_B>
__device__ __forceinline__ void vq_work(
    int n0, int n1, bool bvalid, int l,
    const float* __restrict__ z,
    const float* __restrict__ cs, const float* __restrict__ w2s,
    float* __restrict__ out, int out_size)
{
    const int n1c = bvalid ? n1 : n0;   // safe index for loads

    float hA[DN], hB[DN];
    {
        const int b0 = n0 >> 10,  s0 = n0 & 1023;
        const float* za = z + (size_t)b0 * (128 * 1024) + (size_t)(l * DN) * 1024 + s0;
        #pragma unroll
        for (int d = 0; d < DN; d++) hA[d] = za[(size_t)d * 1024];
        if (DO_B) {
            const int b1 = n1c >> 10, s1 = n1c & 1023;
            const float* zb = z + (size_t)b1 * (128 * 1024) + (size_t)(l * DN) * 1024 + s1;
            #pragma unroll
            for (int d = 0; d < DN; d++) hB[d] = zb[(size_t)d * 1024];
        }
    }
    float h2A = 0.f, h2B = 0.f;
    #pragma unroll
    for (int d = 0; d < DN; d++) h2A = __fadd_rn(h2A, __fmul_rn(hA[d], hA[d]));
    if (DO_B) {
        #pragma unroll
        for (int d = 0; d < DN; d++) h2B = __fadd_rn(h2B, __fmul_rn(hB[d], hB[d]));
    }

    float bA0 = 3.4e38f, bA1 = 3.4e38f, bB0 = 3.4e38f, bB1 = 3.4e38f;
    int   kA0 = 0, kB0 = 0;
    float SA = 0.f, SB = 0.f;
    f2 accA[8], accB[8];
    #pragma unroll
    for (int i = 0; i < 8; i++) { accA[i] = 0ull; accB[i] = 0ull; }

    const ulonglong2* qp = reinterpret_cast<const ulonglong2*>(cs);

    #pragma unroll 4
    for (int k = 0; k < KN; k++) {
        ulonglong2 A = qp[k * 4 + 0];
        ulonglong2 B = qp[k * 4 + 1];
        ulonglong2 C = qp[k * 4 + 2];
        ulonglong2 D = qp[k * 4 + 3];
        float w2 = w2s[k];

        float q0,q1,q2,q3,q4,q5,q6,q7,q8,q9,q10,q11,q12,q13,q14,q15;
        unpack2(A.x, q0,  q1);  unpack2(A.y, q2,  q3);
        unpack2(B.x, q4,  q5);  unpack2(B.y, q6,  q7);
        unpack2(C.x, q8,  q9);  unpack2(C.y, q10, q11);
        unpack2(D.x, q12, q13); unpack2(D.y, q14, q15);

        // exact sequential dots (reference contraction order)
        float dA = 0.f, dB = 0.f;
        dA = fmaf(hA[0],q0,dA);   if (DO_B) dB = fmaf(hB[0],q0,dB);
        dA = fmaf(hA[1],q1,dA);   if (DO_B) dB = fmaf(hB[1],q1,dB);
        dA = fmaf(hA[2],q2,dA);   if (DO_B) dB = fmaf(hB[2],q2,dB);
        dA = fmaf(hA[3],q3,dA);   if (DO_B) dB = fmaf(hB[3],q3,dB);
        dA = fmaf(hA[4],q4,dA);   if (DO_B) dB = fmaf(hB[4],q4,dB);
        dA = fmaf(hA[5],q5,dA);   if (DO_B) dB = fmaf(hB[5],q5,dB);
        dA = fmaf(hA[6],q6,dA);   if (DO_B) dB = fmaf(hB[6],q6,dB);
        dA = fmaf(hA[7],q7,dA);   if (DO_B) dB = fmaf(hB[7],q7,dB);
        dA = fmaf(hA[8],q8,dA);   if (DO_B) dB = fmaf(hB[8],q8,dB);
        dA = fmaf(hA[9],q9,dA);   if (DO_B) dB = fmaf(hB[9],q9,dB);
        dA = fmaf(hA[10],q10,dA); if (DO_B) dB = fmaf(hB[10],q10,dB);
        dA = fmaf(hA[11],q11,dA); if (DO_B) dB = fmaf(hB[11],q11,dB);
        dA = fmaf(hA[12],q12,dA); if (DO_B) dB = fmaf(hB[12],q12,dB);
        dA = fmaf(hA[13],q13,dA); if (DO_B) dB = fmaf(hB[13],q13,dB);
        dA = fmaf(hA[14],q14,dA); if (DO_B) dB = fmaf(hB[14],q14,dB);
        dA = fmaf(hA[15],q15,dA); if (DO_B) dB = fmaf(hB[15],q15,dB);

        float d2A = __fadd_rn(fmaf(-2.0f, dA, h2A), w2);

        float oA = bA0; bool lA = d2A < bA0;
        bA0 = lA ? d2A : bA0;  kA0 = lA ? k : kA0;
        bA1 = fminf(bA1, fmaxf(oA, d2A));

        float wA = expneg_approx(sqrt_approx(fmaxf(d2A, 1e-12f)));
        SA += wA;
        f2 wpA = pack2(wA, wA);
        accA[0] = fma2(wpA, A.x, accA[0]);
        accA[1] = fma2(wpA, A.y, accA[1]);
        accA[2] = fma2(wpA, B.x, accA[2]);
        accA[3] = fma2(wpA, B.y, accA[3]);
        accA[4] = fma2(wpA, C.x, accA[4]);
        accA[5] = fma2(wpA, C.y, accA[5]);
        accA[6] = fma2(wpA, D.x, accA[6]);
        accA[7] = fma2(wpA, D.y, accA[7]);

        if (DO_B) {
            float d2B = __fadd_rn(fmaf(-2.0f, dB, h2B), w2);

            float oB = bB0; bool lB = d2B < bB0;
            bB0 = lB ? d2B : bB0;  kB0 = lB ? k : kB0;
            bB1 = fminf(bB1, fmaxf(oB, d2B));

            float wB = expneg_approx(sqrt_approx(fmaxf(d2B, 1e-12f)));
            SB += wB;
            f2 wpB = pack2(wB, wB);
            accB[0] = fma2(wpB, A.x, accB[0]);
            accB[1] = fma2(wpB, A.y, accB[1]);
            accB[2] = fma2(wpB, B.x, accB[2]);
            accB[3] = fma2(wpB, B.y, accB[3]);
            accB[4] = fma2(wpB, C.x, accB[4]);
            accB[5] = fma2(wpB, C.y, accB[5]);
            accB[6] = fma2(wpB, D.x, accB[6]);
            accB[7] = fma2(wpB, D.y, accB[7]);
        }
    }

    finish_pos(hA, h2A, bA0, bA1, kA0, SA, accA, n0, l, cs, w2s, out, out_size);
    if (DO_B && bvalid)
        finish_pos(hB, h2B, bB0, bB1, kB0, SB, accB, n1, l, cs, w2s, out, out_size);
}

__global__ __launch_bounds__(128, 4)
void vq_kernel(const float* __restrict__ z,
               const float* __restrict__ codes,
               float* __restrict__ out,
               int out_size)
{
    __shared__ __align__(16) float cs[KN * DN];   // codes[l], [k][d], 32 KB
    __shared__ float w2s[KN];                     // ||codes[l][k]||^2 (ref order)

    const int l = blockIdx.y;
    const int t = threadIdx.x;

    // ---- cooperative load of codes[l] ----
    {
        const float4* cg = reinterpret_cast<const float4*>(codes + (size_t)l * KN * DN);
        float4* cs4 = reinterpret_cast<float4*>(cs);
        #pragma unroll 4
        for (int i = t; i < KN * DN / 4; i += 128) cs4[i] = cg[i];
    }
    __syncthreads();
    for (int k = t; k < KN; k += 128) {
        const float* c = cs + k * DN;
        float a = 0.f;
        #pragma unroll
        for (int d = 0; d < DN; d++) a = __fadd_rn(a, __fmul_rn(c[d], c[d]));
        w2s[k] = a;
    }
    __syncthreads();

    const int base = blockIdx.x * BLKPOS;
    const int n0 = base + t;             // always < NPOS (max 16333)
    const int n1 = base + 128 + t;       // stream B: valid iff t<94 && n1<NPOS
    const bool bvalid = (t < 94) && (n1 < NPOS);

    if (t < 96) {   // warps 0-2: dual stream
        vq_work<true>(n0, n1, bvalid, l, z, cs, w2s, out, out_size);
    } else {        // warp 3: single stream
        vq_work<false>(n0, 0, false, l, z, cs, w2s, out, out_size);
    }
}

extern "C" void kernel_launch(void* const* d_in, const int* in_sizes, int n_in,
                              void* d_out, int out_size) {
    const float* z     = (const float*)d_in[0];
    const float* codes = (const float*)d_in[1];
    float* out = (float*)d_out;

    dim3 grid(74, LN);   // 592 blocks = 148 SMs x 4 CTAs, perfectly balanced
    vq_kernel<<<grid, 128>>>(z, codes, out, out_size);
}